// round 6
// baseline (speedup 1.0000x reference)
#include <cuda_runtime.h>
#include <cuda_fp16.h>
#include <cstdint>

namespace {

constexpr int THREADS = 256;
constexpr int NWARP   = 8;
constexpr int MT      = 2;               // 16-row m-tiles per warp
constexpr int WARP_M  = 16 * MT;         // 32 rows / warp
constexpr int CTA_M   = NWARP * WARP_M;  // 256 rows / CTA
constexpr int LDD     = 24;              // density smem ld (halves), conflict-free

struct SmemLayout {
    __half w_d0[64 * 40];   // B col-major: (k,n) -> n*LDB + k
    __half w_c0[64 * 40];
    __half w_d1[16 * 72];
    __half w_c3[16 * 72];
    __half w_c1[64 * 72];
    __half w_c2[64 * 72];
    // den: d1 outputs (16 half cols) + sigma f32 at half-cols 16..17
    __half den[NWARP][WARP_M * LDD];
};  // 45568 B static -> 3 CTAs/SM fits

__device__ __forceinline__ uint32_t h2u(float x, float y) {
    __half2 h = __floats2half2_rn(x, y);
    return *reinterpret_cast<uint32_t*>(&h);
}
__device__ __forceinline__ uint32_t hh2u(__half x, __half y) {
    __half2 h = __halves2half2(x, y);
    return *reinterpret_cast<uint32_t*>(&h);
}

__device__ __forceinline__ void mma16816(float c[4], const uint32_t a[4],
                                         uint32_t b0, uint32_t b1) {
    asm volatile(
        "mma.sync.aligned.m16n8k16.row.col.f32.f16.f16.f32 "
        "{%0,%1,%2,%3},{%4,%5,%6,%7},{%8,%9},{%0,%1,%2,%3};\n"
        : "+f"(c[0]), "+f"(c[1]), "+f"(c[2]), "+f"(c[3])
        : "r"(a[0]), "r"(a[1]), "r"(a[2]), "r"(a[3]), "r"(b0), "r"(b1));
}

// Register-chained relu layer, MT m-tiles sharing every B fragment.
// A/O are [MT][4][4]; only the first KT k-frags of A are read.
template <int KT, int NPAIR, int LDB>
__device__ __forceinline__ void layer_chain(const uint32_t (&A)[MT][4][4],
                                            const __half* __restrict__ wg,
                                            uint32_t (&O)[MT][4][4]) {
#pragma unroll
    for (int np = 0; np < NPAIR; np++) {
        float acc[MT][2][4];
#pragma unroll
        for (int m = 0; m < MT; m++)
#pragma unroll
            for (int h = 0; h < 2; h++)
#pragma unroll
                for (int e = 0; e < 4; e++) acc[m][h][e] = 0.0f;
#pragma unroll
        for (int k = 0; k < KT; k++) {
#pragma unroll
            for (int h = 0; h < 2; h++) {
                const __half* bp = wg + (np * 16 + h * 8) * LDB + k * 16;
                uint32_t b0 = *reinterpret_cast<const uint32_t*>(bp);
                uint32_t b1 = *reinterpret_cast<const uint32_t*>(bp + 8);
#pragma unroll
                for (int m = 0; m < MT; m++) mma16816(acc[m][h], A[m][k], b0, b1);
            }
        }
#pragma unroll
        for (int m = 0; m < MT; m++) {
            O[m][np][0] = h2u(fmaxf(acc[m][0][0], 0.f), fmaxf(acc[m][0][1], 0.f));
            O[m][np][1] = h2u(fmaxf(acc[m][0][2], 0.f), fmaxf(acc[m][0][3], 0.f));
            O[m][np][2] = h2u(fmaxf(acc[m][1][0], 0.f), fmaxf(acc[m][1][1], 0.f));
            O[m][np][3] = h2u(fmaxf(acc[m][1][2], 0.f), fmaxf(acc[m][1][3], 0.f));
        }
    }
}

}  // namespace

__global__ void __launch_bounds__(THREADS, 3)
nerf_fused_kernel(const float* __restrict__ hash, const float* __restrict__ sh,
                  const float* __restrict__ d0, const float* __restrict__ d1,
                  const float* __restrict__ c0, const float* __restrict__ c1,
                  const float* __restrict__ c2, const float* __restrict__ c3,
                  float* __restrict__ out, int n_tiles) {
    __shared__ SmemLayout S;
    const int tid  = threadIdx.x;
    const int warp = tid >> 5;
    const int lane = tid & 31;
    const int g    = lane >> 2;       // row-in-tile-half
    const int i2   = (lane & 3) * 2;  // column pair base

    // ---- Stage weights to SMEM fp16 once per CTA ----
    for (int i = tid; i < 64 * 32; i += THREADS)
        S.w_d0[(i >> 5) * 40 + (i & 31)] = __float2half(d0[i]);
    for (int i = tid; i < 16 * 64; i += THREADS)
        S.w_d1[(i >> 6) * 72 + (i & 63)] = __float2half(d1[i]);
    for (int i = tid; i < 64 * 32; i += THREADS) {
        int n = i >> 5, k = i & 31;
        S.w_c0[n * 40 + k] = __float2half(k < 31 ? c0[n * 31 + k] : 0.0f);
    }
    for (int i = tid; i < 64 * 64; i += THREADS) {
        int n = i >> 6, k = i & 63;
        S.w_c1[n * 72 + k] = __float2half(c1[i]);
        S.w_c2[n * 72 + k] = __float2half(c2[i]);
    }
    for (int i = tid; i < 16 * 64; i += THREADS) {
        int n = i >> 6, k = i & 63;
        S.w_c3[n * 72 + k] = __float2half(n < 3 ? c3[n * 64 + k] : 0.0f);
    }
    __syncthreads();  // only block barrier

    __half* den = S.den[warp];
    const int o40 = g * 40 + i2;
    const int o72 = g * 72 + i2;
    float4* out4 = reinterpret_cast<float4*>(out);

    for (int tile = blockIdx.x; tile < n_tiles; tile += gridDim.x) {
        const size_t row0 = (size_t)tile * CTA_M + warp * WARP_M;

        uint32_t Aa[MT][4][4];  // ping
        uint32_t Ab[MT][4][4];  // pong (k-frags 0..1 double as 32-wide inputs)

        // ---- hash A frags straight from gmem ----
#pragma unroll
        for (int m = 0; m < MT; m++) {
            const float* h0 = hash + (row0 + m * 16 + g) * 32;
            const float* h8 = hash + (row0 + m * 16 + g + 8) * 32;
#pragma unroll
            for (int kt = 0; kt < 2; kt++) {
                Ab[m][kt][0] = h2u(h0[kt * 16 + i2],     h0[kt * 16 + i2 + 1]);
                Ab[m][kt][1] = h2u(h8[kt * 16 + i2],     h8[kt * 16 + i2 + 1]);
                Ab[m][kt][2] = h2u(h0[kt * 16 + i2 + 8], h0[kt * 16 + i2 + 9]);
                Ab[m][kt][3] = h2u(h8[kt * 16 + i2 + 8], h8[kt * 16 + i2 + 9]);
            }
        }

        // ---- d0: relu(hash @ d0^T) ----
        layer_chain<2, 4, 40>(Ab, S.w_d0 + o40, Aa);

        // ---- d1: h @ d1^T -> density (den, half) + sigma (den, f32) ----
        {
            float dacc[MT][2][4];
#pragma unroll
            for (int m = 0; m < MT; m++)
#pragma unroll
                for (int h = 0; h < 2; h++)
#pragma unroll
                    for (int e = 0; e < 4; e++) dacc[m][h][e] = 0.0f;
#pragma unroll
            for (int k = 0; k < 4; k++) {
#pragma unroll
                for (int h = 0; h < 2; h++) {
                    const __half* bp = S.w_d1 + o72 + h * 8 * 72 + k * 16;
                    uint32_t b0 = *reinterpret_cast<const uint32_t*>(bp);
                    uint32_t b1 = *reinterpret_cast<const uint32_t*>(bp + 8);
#pragma unroll
                    for (int m = 0; m < MT; m++) mma16816(dacc[m][h], Aa[m][k], b0, b1);
                }
            }
#pragma unroll
            for (int m = 0; m < MT; m++) {
                __half* dm = den + m * 16 * LDD;
                *reinterpret_cast<uint32_t*>(dm + g * LDD + i2) =
                    h2u(dacc[m][0][0], dacc[m][0][1]);
                *reinterpret_cast<uint32_t*>(dm + (g + 8) * LDD + i2) =
                    h2u(dacc[m][0][2], dacc[m][0][3]);
                *reinterpret_cast<uint32_t*>(dm + g * LDD + i2 + 8) =
                    h2u(dacc[m][1][0], dacc[m][1][1]);
                *reinterpret_cast<uint32_t*>(dm + (g + 8) * LDD + i2 + 8) =
                    h2u(dacc[m][1][2], dacc[m][1][3]);
                if (i2 == 0) {  // sigma f32 at half-cols 16..17
                    *reinterpret_cast<float*>(dm + g * LDD + 16)       = dacc[m][0][0];
                    *reinterpret_cast<float*>(dm + (g + 8) * LDD + 16) = dacc[m][0][2];
                }
            }
        }
        __syncwarp();

        // ---- c0 input: k-tile0 = sh (gmem), k-tile1 = shifted density ----
        {
            __half z = __float2half(0.0f);
#pragma unroll
            for (int m = 0; m < MT; m++) {
                const float* s0 = sh + (row0 + m * 16 + g) * 16;
                const float* s8 = sh + (row0 + m * 16 + g + 8) * 16;
                const __half* dm = den + m * 16 * LDD;
                Ab[m][0][0] = h2u(s0[i2],     s0[i2 + 1]);
                Ab[m][0][1] = h2u(s8[i2],     s8[i2 + 1]);
                Ab[m][0][2] = h2u(s0[i2 + 8], s0[i2 + 9]);
                Ab[m][0][3] = h2u(s8[i2 + 8], s8[i2 + 9]);
                // concat col 16+j = d1 col j+1 (shift by one); col 31 -> 0
                __half hiA = (i2 == 6) ? z : dm[g * LDD + i2 + 10];
                __half hiB = (i2 == 6) ? z : dm[(g + 8) * LDD + i2 + 10];
                Ab[m][1][0] = hh2u(dm[g * LDD + i2 + 1],       dm[g * LDD + i2 + 2]);
                Ab[m][1][1] = hh2u(dm[(g + 8) * LDD + i2 + 1], dm[(g + 8) * LDD + i2 + 2]);
                Ab[m][1][2] = hh2u(dm[g * LDD + i2 + 9],       hiA);
                Ab[m][1][3] = hh2u(dm[(g + 8) * LDD + i2 + 9], hiB);
            }
        }

        // ---- c0, c1, c2: register-chained relu layers ----
        layer_chain<2, 4, 40>(Ab, S.w_c0 + o40, Aa);
        layer_chain<4, 4, 72>(Aa, S.w_c1 + o72, Ab);
        layer_chain<4, 4, 72>(Ab, S.w_c2 + o72, Aa);

        // ---- c3: color (cols 0..2 of one 8-wide n-tile) ----
        {
            float cacc[MT][4];
#pragma unroll
            for (int m = 0; m < MT; m++)
#pragma unroll
                for (int e = 0; e < 4; e++) cacc[m][e] = 0.0f;
#pragma unroll
            for (int k = 0; k < 4; k++) {
                const __half* bp = S.w_c3 + o72 + k * 16;
                uint32_t b0 = *reinterpret_cast<const uint32_t*>(bp);
                uint32_t b1 = *reinterpret_cast<const uint32_t*>(bp + 8);
#pragma unroll
                for (int m = 0; m < MT; m++) mma16816(cacc[m], Aa[m][k], b0, b1);
            }
#pragma unroll
            for (int m = 0; m < MT; m++) {
                // lane 4g holds cols {0,1}; lane 4g+1 holds col 2
                float b0c = __shfl_down_sync(0xffffffffu, cacc[m][0], 1);
                float b1c = __shfl_down_sync(0xffffffffu, cacc[m][2], 1);
                if ((lane & 3) == 0) {
                    const __half* dm = den + m * 16 * LDD;
                    float s0 = *reinterpret_cast<const float*>(dm + g * LDD + 16);
                    float s1 = *reinterpret_cast<const float*>(dm + (g + 8) * LDD + 16);
                    out4[row0 + m * 16 + g]     = make_float4(cacc[m][0], cacc[m][1], b0c, s0);
                    out4[row0 + m * 16 + g + 8] = make_float4(cacc[m][2], cacc[m][3], b1c, s1);
                }
            }
        }
        __syncwarp();
    }
}

extern "C" void kernel_launch(void* const* d_in, const int* in_sizes, int n_in,
                              void* d_out, int out_size) {
    const float* hash = (const float*)d_in[0];  // [N, 32]
    const float* sh   = (const float*)d_in[1];  // [N, 16]
    const float* d0   = (const float*)d_in[2];  // [64, 32]
    const float* d1   = (const float*)d_in[3];  // [16, 64]
    const float* c0   = (const float*)d_in[4];  // [64, 31]
    const float* c1   = (const float*)d_in[5];  // [64, 64]
    const float* c2   = (const float*)d_in[6];  // [64, 64]
    const float* c3   = (const float*)d_in[7];  // [3, 64]
    float* out = (float*)d_out;                 // [N, 4]

    const int n       = in_sizes[0] / 32;
    const int n_tiles = n / CTA_M;  // 8192

    int grid = 148 * 3;  // persistent, 3 CTAs/SM
    if (grid > n_tiles) grid = n_tiles;

    nerf_fused_kernel<<<grid, THREADS>>>(hash, sh, d0, d1, c0, c1, c2, c3, out,
                                         n_tiles);
}

// round 7
// speedup vs baseline: 1.2100x; 1.2100x over previous
#include <cuda_runtime.h>
#include <cuda_fp16.h>
#include <cstdint>

namespace {

constexpr int THREADS = 128;             // 4 warps/CTA -> 5 CTAs/SM, ~102 regs
constexpr int NWARP   = 4;
constexpr int MT      = 2;               // 16-row m-tiles per warp
constexpr int WARP_M  = 16 * MT;         // 32 rows / warp
constexpr int CTA_M   = NWARP * WARP_M;  // 128 rows / CTA
constexpr int LDD     = 24;              // density smem ld (halves), conflict-free

struct SmemLayout {
    __half w_d0[64 * 40];   // B col-major: (k,n) -> n*LDB + k
    __half w_c0[64 * 40];
    __half w_d1[16 * 72];
    __half w_c3[16 * 72];
    __half w_c1[64 * 72];
    __half w_c2[64 * 72];
    // den: d1 outputs (16 half cols) + sigma f32 at half-cols 16..17
    __half den[NWARP][WARP_M * LDD];
};  // 39424 B -> 5 CTAs/SM fits (197 KB)

__device__ __forceinline__ uint32_t h2u(float x, float y) {
    __half2 h = __floats2half2_rn(x, y);
    return *reinterpret_cast<uint32_t*>(&h);
}
__device__ __forceinline__ uint32_t hh2u(__half x, __half y) {
    __half2 h = __halves2half2(x, y);
    return *reinterpret_cast<uint32_t*>(&h);
}

__device__ __forceinline__ void mma16816(float c[4], const uint32_t a[4],
                                         uint32_t b0, uint32_t b1) {
    asm volatile(
        "mma.sync.aligned.m16n8k16.row.col.f32.f16.f16.f32 "
        "{%0,%1,%2,%3},{%4,%5,%6,%7},{%8,%9},{%0,%1,%2,%3};\n"
        : "+f"(c[0]), "+f"(c[1]), "+f"(c[2]), "+f"(c[3])
        : "r"(a[0]), "r"(a[1]), "r"(a[2]), "r"(a[3]), "r"(b0), "r"(b1));
}

// Register-chained relu layer, MT m-tiles sharing every B fragment.
template <int KT, int NPAIR, int LDB>
__device__ __forceinline__ void layer_chain(const uint32_t (&A)[MT][4][4],
                                            const __half* __restrict__ wg,
                                            uint32_t (&O)[MT][4][4]) {
#pragma unroll
    for (int np = 0; np < NPAIR; np++) {
        float acc[MT][2][4];
#pragma unroll
        for (int m = 0; m < MT; m++)
#pragma unroll
            for (int h = 0; h < 2; h++)
#pragma unroll
                for (int e = 0; e < 4; e++) acc[m][h][e] = 0.0f;
#pragma unroll
        for (int k = 0; k < KT; k++) {
#pragma unroll
            for (int h = 0; h < 2; h++) {
                const __half* bp = wg + (np * 16 + h * 8) * LDB + k * 16;
                uint32_t b0 = *reinterpret_cast<const uint32_t*>(bp);
                uint32_t b1 = *reinterpret_cast<const uint32_t*>(bp + 8);
#pragma unroll
                for (int m = 0; m < MT; m++) mma16816(acc[m][h], A[m][k], b0, b1);
            }
        }
#pragma unroll
        for (int m = 0; m < MT; m++) {
            O[m][np][0] = h2u(fmaxf(acc[m][0][0], 0.f), fmaxf(acc[m][0][1], 0.f));
            O[m][np][1] = h2u(fmaxf(acc[m][0][2], 0.f), fmaxf(acc[m][0][3], 0.f));
            O[m][np][2] = h2u(fmaxf(acc[m][1][0], 0.f), fmaxf(acc[m][1][1], 0.f));
            O[m][np][3] = h2u(fmaxf(acc[m][1][2], 0.f), fmaxf(acc[m][1][3], 0.f));
        }
    }
}

}  // namespace

__global__ void __launch_bounds__(THREADS, 5)
nerf_fused_kernel(const float* __restrict__ hash, const float* __restrict__ sh,
                  const float* __restrict__ d0, const float* __restrict__ d1,
                  const float* __restrict__ c0, const float* __restrict__ c1,
                  const float* __restrict__ c2, const float* __restrict__ c3,
                  float* __restrict__ out, int n_tiles) {
    __shared__ SmemLayout S;
    const int tid  = threadIdx.x;
    const int warp = tid >> 5;
    const int lane = tid & 31;
    const int g    = lane >> 2;       // row-in-tile-half
    const int i2   = (lane & 3) * 2;  // column pair base

    // ---- Stage weights to SMEM fp16 once per CTA ----
    for (int i = tid; i < 64 * 32; i += THREADS)
        S.w_d0[(i >> 5) * 40 + (i & 31)] = __float2half(d0[i]);
    for (int i = tid; i < 16 * 64; i += THREADS)
        S.w_d1[(i >> 6) * 72 + (i & 63)] = __float2half(d1[i]);
    for (int i = tid; i < 64 * 32; i += THREADS) {
        int n = i >> 5, k = i & 31;
        S.w_c0[n * 40 + k] = __float2half(k < 31 ? c0[n * 31 + k] : 0.0f);
    }
    for (int i = tid; i < 64 * 64; i += THREADS) {
        int n = i >> 6, k = i & 63;
        S.w_c1[n * 72 + k] = __float2half(c1[i]);
        S.w_c2[n * 72 + k] = __float2half(c2[i]);
    }
    for (int i = tid; i < 16 * 64; i += THREADS) {
        int n = i >> 6, k = i & 63;
        S.w_c3[n * 72 + k] = __float2half(n < 3 ? c3[n * 64 + k] : 0.0f);
    }
    __syncthreads();  // only block barrier

    __half* den = S.den[warp];
    const int o40 = g * 40 + i2;
    const int o72 = g * 72 + i2;
    float4* out4 = reinterpret_cast<float4*>(out);

    for (int tile = blockIdx.x; tile < n_tiles; tile += gridDim.x) {
        const size_t row0 = (size_t)tile * CTA_M + warp * WARP_M;

        uint32_t Aa[MT][4][4];  // ping
        uint32_t Ab[MT][4][4];  // pong (k-frags 0..1 double as 32-wide inputs)

        // ---- hash A frags straight from gmem ----
#pragma unroll
        for (int m = 0; m < MT; m++) {
            const float* h0 = hash + (row0 + m * 16 + g) * 32;
            const float* h8 = hash + (row0 + m * 16 + g + 8) * 32;
#pragma unroll
            for (int kt = 0; kt < 2; kt++) {
                Ab[m][kt][0] = h2u(h0[kt * 16 + i2],     h0[kt * 16 + i2 + 1]);
                Ab[m][kt][1] = h2u(h8[kt * 16 + i2],     h8[kt * 16 + i2 + 1]);
                Ab[m][kt][2] = h2u(h0[kt * 16 + i2 + 8], h0[kt * 16 + i2 + 9]);
                Ab[m][kt][3] = h2u(h8[kt * 16 + i2 + 8], h8[kt * 16 + i2 + 9]);
            }
        }

        // ---- d0: relu(hash @ d0^T) ----
        layer_chain<2, 4, 40>(Ab, S.w_d0 + o40, Aa);

        // ---- d1: h @ d1^T -> density (den, half) + sigma (den, f32) ----
        {
            float dacc[MT][2][4];
#pragma unroll
            for (int m = 0; m < MT; m++)
#pragma unroll
                for (int h = 0; h < 2; h++)
#pragma unroll
                    for (int e = 0; e < 4; e++) dacc[m][h][e] = 0.0f;
#pragma unroll
            for (int k = 0; k < 4; k++) {
#pragma unroll
                for (int h = 0; h < 2; h++) {
                    const __half* bp = S.w_d1 + o72 + h * 8 * 72 + k * 16;
                    uint32_t b0 = *reinterpret_cast<const uint32_t*>(bp);
                    uint32_t b1 = *reinterpret_cast<const uint32_t*>(bp + 8);
#pragma unroll
                    for (int m = 0; m < MT; m++) mma16816(dacc[m][h], Aa[m][k], b0, b1);
                }
            }
#pragma unroll
            for (int m = 0; m < MT; m++) {
                __half* dm = den + m * 16 * LDD;
                *reinterpret_cast<uint32_t*>(dm + g * LDD + i2) =
                    h2u(dacc[m][0][0], dacc[m][0][1]);
                *reinterpret_cast<uint32_t*>(dm + (g + 8) * LDD + i2) =
                    h2u(dacc[m][0][2], dacc[m][0][3]);
                *reinterpret_cast<uint32_t*>(dm + g * LDD + i2 + 8) =
                    h2u(dacc[m][1][0], dacc[m][1][1]);
                *reinterpret_cast<uint32_t*>(dm + (g + 8) * LDD + i2 + 8) =
                    h2u(dacc[m][1][2], dacc[m][1][3]);
                if (i2 == 0) {  // sigma f32 at half-cols 16..17
                    *reinterpret_cast<float*>(dm + g * LDD + 16)       = dacc[m][0][0];
                    *reinterpret_cast<float*>(dm + (g + 8) * LDD + 16) = dacc[m][0][2];
                }
            }
        }
        __syncwarp();

        // ---- c0 input: k-tile0 = sh (gmem), k-tile1 = shifted density ----
        {
            __half z = __float2half(0.0f);
#pragma unroll
            for (int m = 0; m < MT; m++) {
                const float* s0 = sh + (row0 + m * 16 + g) * 16;
                const float* s8 = sh + (row0 + m * 16 + g + 8) * 16;
                const __half* dm = den + m * 16 * LDD;
                Ab[m][0][0] = h2u(s0[i2],     s0[i2 + 1]);
                Ab[m][0][1] = h2u(s8[i2],     s8[i2 + 1]);
                Ab[m][0][2] = h2u(s0[i2 + 8], s0[i2 + 9]);
                Ab[m][0][3] = h2u(s8[i2 + 8], s8[i2 + 9]);
                // concat col 16+j = d1 col j+1 (shift by one); col 31 -> 0
                __half hiA = (i2 == 6) ? z : dm[g * LDD + i2 + 10];
                __half hiB = (i2 == 6) ? z : dm[(g + 8) * LDD + i2 + 10];
                Ab[m][1][0] = hh2u(dm[g * LDD + i2 + 1],       dm[g * LDD + i2 + 2]);
                Ab[m][1][1] = hh2u(dm[(g + 8) * LDD + i2 + 1], dm[(g + 8) * LDD + i2 + 2]);
                Ab[m][1][2] = hh2u(dm[g * LDD + i2 + 9],       hiA);
                Ab[m][1][3] = hh2u(dm[(g + 8) * LDD + i2 + 9], hiB);
            }
        }

        // ---- c0, c1, c2: register-chained relu layers ----
        layer_chain<2, 4, 40>(Ab, S.w_c0 + o40, Aa);
        layer_chain<4, 4, 72>(Aa, S.w_c1 + o72, Ab);
        layer_chain<4, 4, 72>(Ab, S.w_c2 + o72, Aa);

        // ---- c3: color (cols 0..2 of one 8-wide n-tile) ----
        {
            float cacc[MT][4];
#pragma unroll
            for (int m = 0; m < MT; m++)
#pragma unroll
                for (int e = 0; e < 4; e++) cacc[m][e] = 0.0f;
#pragma unroll
            for (int k = 0; k < 4; k++) {
                const __half* bp = S.w_c3 + o72 + k * 16;
                uint32_t b0 = *reinterpret_cast<const uint32_t*>(bp);
                uint32_t b1 = *reinterpret_cast<const uint32_t*>(bp + 8);
#pragma unroll
                for (int m = 0; m < MT; m++) mma16816(cacc[m], Aa[m][k], b0, b1);
            }
#pragma unroll
            for (int m = 0; m < MT; m++) {
                // lane 4g holds cols {0,1}; lane 4g+1 holds col 2
                float b0c = __shfl_down_sync(0xffffffffu, cacc[m][0], 1);
                float b1c = __shfl_down_sync(0xffffffffu, cacc[m][2], 1);
                if ((lane & 3) == 0) {
                    const __half* dm = den + m * 16 * LDD;
                    float s0 = *reinterpret_cast<const float*>(dm + g * LDD + 16);
                    float s1 = *reinterpret_cast<const float*>(dm + (g + 8) * LDD + 16);
                    out4[row0 + m * 16 + g]     = make_float4(cacc[m][0], cacc[m][1], b0c, s0);
                    out4[row0 + m * 16 + g + 8] = make_float4(cacc[m][2], cacc[m][3], b1c, s1);
                }
            }
        }
        __syncwarp();
    }
}

extern "C" void kernel_launch(void* const* d_in, const int* in_sizes, int n_in,
                              void* d_out, int out_size) {
    const float* hash = (const float*)d_in[0];  // [N, 32]
    const float* sh   = (const float*)d_in[1];  // [N, 16]
    const float* d0   = (const float*)d_in[2];  // [64, 32]
    const float* d1   = (const float*)d_in[3];  // [16, 64]
    const float* c0   = (const float*)d_in[4];  // [64, 31]
    const float* c1   = (const float*)d_in[5];  // [64, 64]
    const float* c2   = (const float*)d_in[6];  // [64, 64]
    const float* c3   = (const float*)d_in[7];  // [3, 64]
    float* out = (float*)d_out;                 // [N, 4]

    const int n       = in_sizes[0] / 32;
    const int n_tiles = n / CTA_M;  // 2097152/128 = 16384

    int grid = 148 * 5;  // persistent, 5 CTAs/SM, 20 warps/SM
    if (grid > n_tiles) grid = n_tiles;

    nerf_fused_kernel<<<grid, THREADS>>>(hash, sh, d0, d1, c0, c1, c2, c3, out,
                                         n_tiles);
}

// round 8
// speedup vs baseline: 1.5558x; 1.2857x over previous
#include <cuda_runtime.h>
#include <cuda_fp16.h>
#include <cstdint>

namespace {

constexpr int THREADS = 128;             // 4 warps/CTA, 5 CTAs/SM -> 20 warps
constexpr int NWARP   = 4;
constexpr int MT      = 2;               // 16-row m-tiles per warp
constexpr int WARP_M  = 16 * MT;         // 32 rows / warp
constexpr int CTA_M   = NWARP * WARP_M;  // 128 rows / CTA
constexpr int LDD     = 24;              // density smem ld (halves), conflict-free

// Per-lane permuted weight tables. Entry (nph, c, lane) is one uint4 = the
// (b0,b1) fragment pairs for k-tiles 2c and 2c+1 of n-group nph, exactly as
// lane `lane` consumes them in mma.m16n8k16. 16B lane stride -> conflict-free
// LDS.128.
struct SmemLayout {
    uint4 p_d0[8 * 1 * 32];  // NPH=8 (np4 x h2), CH=1 (KT=2)   4 KB
    uint4 p_c0[8 * 1 * 32];  //                                  4 KB
    uint4 p_d1[2 * 2 * 32];  // NPH=2 (np1 x h2), CH=2 (KT=4)   2 KB
    uint4 p_c1[8 * 2 * 32];  // NPH=8, CH=2                      8 KB
    uint4 p_c2[8 * 2 * 32];  //                                  8 KB
    uint4 p_c3[1 * 2 * 32];  // NPH=1 (h=0 only), CH=2           1 KB
    // den: d1 outputs (16 half cols) + sigma f32 at half-cols 16..17
    __half den[NWARP][WARP_M * LDD];  // 6 KB
};  // ~33 KB -> 5 CTAs/SM

__device__ __forceinline__ uint32_t h2u(float x, float y) {
    __half2 h = __floats2half2_rn(x, y);
    return *reinterpret_cast<uint32_t*>(&h);
}
__device__ __forceinline__ uint32_t hh2u(__half x, __half y) {
    __half2 h = __halves2half2(x, y);
    return *reinterpret_cast<uint32_t*>(&h);
}

__device__ __forceinline__ void mma16816(float c[4], const uint32_t a[4],
                                         uint32_t b0, uint32_t b1) {
    asm volatile(
        "mma.sync.aligned.m16n8k16.row.col.f32.f16.f16.f32 "
        "{%0,%1,%2,%3},{%4,%5,%6,%7},{%8,%9},{%0,%1,%2,%3};\n"
        : "+f"(c[0]), "+f"(c[1]), "+f"(c[2]), "+f"(c[3])
        : "r"(a[0]), "r"(a[1]), "r"(a[2]), "r"(a[3]), "r"(b0), "r"(b1));
}

// Stage a [Nout x Kin] f32 row-major weight matrix into the permuted table.
// dst entry e = (nph*CH + c)*32 + lane.
__device__ void stage_perm(uint4* dst, const float* __restrict__ W, int Nout,
                           int Kin, int NPH, int CH, int tid) {
    const int total = NPH * CH * 32;
    for (int e = tid; e < total; e += THREADS) {
        int lane = e & 31;
        int c    = (e >> 5) % CH;
        int nph  = e / (32 * CH);
        int row  = (nph >> 1) * 16 + (nph & 1) * 8 + (lane >> 2);
        int col  = (lane & 3) * 2;
        int k0   = c * 32;  // k-tile (2c) column base
        auto rd = [&](int cc) -> float {
            return (row < Nout && cc < Kin) ? W[row * Kin + cc] : 0.0f;
        };
        uint4 v;
        v.x = h2u(rd(k0 + col),      rd(k0 + col + 1));   // k=2c   b0
        v.y = h2u(rd(k0 + col + 8),  rd(k0 + col + 9));   // k=2c   b1
        v.z = h2u(rd(k0 + 16 + col),     rd(k0 + 16 + col + 1));  // k=2c+1 b0
        v.w = h2u(rd(k0 + 16 + col + 8), rd(k0 + 16 + col + 9));  // k=2c+1 b1
        dst[e] = v;
    }
}

// Register-chained relu layer: one LDS.128 per (np,h,chunk) feeds 2*MT HMMAs.
// pw already offset by +lane.
template <int KT, int NP>
__device__ __forceinline__ void layer_chain(const uint32_t (&A)[MT][4][4],
                                            const uint4* __restrict__ pw,
                                            uint32_t (&O)[MT][4][4]) {
    constexpr int CH = KT / 2;
#pragma unroll
    for (int np = 0; np < NP; np++) {
        float acc[MT][2][4];
#pragma unroll
        for (int m = 0; m < MT; m++)
#pragma unroll
            for (int h = 0; h < 2; h++)
#pragma unroll
                for (int e = 0; e < 4; e++) acc[m][h][e] = 0.0f;
#pragma unroll
        for (int h = 0; h < 2; h++) {
#pragma unroll
            for (int c = 0; c < CH; c++) {
                uint4 v = pw[((np * 2 + h) * CH + c) * 32];
#pragma unroll
                for (int m = 0; m < MT; m++) {
                    mma16816(acc[m][h], A[m][2 * c],     v.x, v.y);
                    mma16816(acc[m][h], A[m][2 * c + 1], v.z, v.w);
                }
            }
        }
#pragma unroll
        for (int m = 0; m < MT; m++) {
            O[m][np][0] = h2u(fmaxf(acc[m][0][0], 0.f), fmaxf(acc[m][0][1], 0.f));
            O[m][np][1] = h2u(fmaxf(acc[m][0][2], 0.f), fmaxf(acc[m][0][3], 0.f));
            O[m][np][2] = h2u(fmaxf(acc[m][1][0], 0.f), fmaxf(acc[m][1][1], 0.f));
            O[m][np][3] = h2u(fmaxf(acc[m][1][2], 0.f), fmaxf(acc[m][1][3], 0.f));
        }
    }
}

}  // namespace

__global__ void __launch_bounds__(THREADS, 5)
nerf_fused_kernel(const float* __restrict__ hash, const float* __restrict__ sh,
                  const float* __restrict__ d0, const float* __restrict__ d1,
                  const float* __restrict__ c0, const float* __restrict__ c1,
                  const float* __restrict__ c2, const float* __restrict__ c3,
                  float* __restrict__ out, int n_tiles) {
    __shared__ SmemLayout S;
    const int tid  = threadIdx.x;
    const int warp = tid >> 5;
    const int lane = tid & 31;
    const int g    = lane >> 2;       // row-in-tile-half
    const int i2   = (lane & 3) * 2;  // column pair base

    // ---- Stage permuted weights once per CTA ----
    stage_perm(S.p_d0, d0, 64, 32, 8, 1, tid);
    stage_perm(S.p_c0, c0, 64, 31, 8, 1, tid);
    stage_perm(S.p_d1, d1, 16, 64, 2, 2, tid);
    stage_perm(S.p_c1, c1, 64, 64, 8, 2, tid);
    stage_perm(S.p_c2, c2, 64, 64, 8, 2, tid);
    stage_perm(S.p_c3, c3,  3, 64, 1, 2, tid);
    __syncthreads();  // only block barrier

    __half* den = S.den[warp];
    const uint4* pw_d0 = S.p_d0 + lane;
    const uint4* pw_c0 = S.p_c0 + lane;
    const uint4* pw_d1 = S.p_d1 + lane;
    const uint4* pw_c1 = S.p_c1 + lane;
    const uint4* pw_c2 = S.p_c2 + lane;
    const uint4* pw_c3 = S.p_c3 + lane;
    float4* out4 = reinterpret_cast<float4*>(out);

    for (int tile = blockIdx.x; tile < n_tiles; tile += gridDim.x) {
        const size_t row0 = (size_t)tile * CTA_M + warp * WARP_M;

        uint32_t Aa[MT][4][4];  // ping
        uint32_t Ab[MT][4][4];  // pong (k-frags 0..1 double as 32-wide inputs)

        // ---- hash A frags straight from gmem (streaming) ----
#pragma unroll
        for (int m = 0; m < MT; m++) {
            const float2* h0 =
                reinterpret_cast<const float2*>(hash + (row0 + m * 16 + g) * 32);
            const float2* h8 =
                reinterpret_cast<const float2*>(hash + (row0 + m * 16 + g + 8) * 32);
#pragma unroll
            for (int kt = 0; kt < 2; kt++) {
                float2 v0 = __ldcs(h0 + kt * 8 + (i2 >> 1));
                float2 v1 = __ldcs(h8 + kt * 8 + (i2 >> 1));
                float2 v2 = __ldcs(h0 + kt * 8 + 4 + (i2 >> 1));
                float2 v3 = __ldcs(h8 + kt * 8 + 4 + (i2 >> 1));
                Ab[m][kt][0] = h2u(v0.x, v0.y);
                Ab[m][kt][1] = h2u(v1.x, v1.y);
                Ab[m][kt][2] = h2u(v2.x, v2.y);
                Ab[m][kt][3] = h2u(v3.x, v3.y);
            }
        }

        // ---- d0: relu(hash @ d0^T) ----
        layer_chain<2, 4>(Ab, pw_d0, Aa);

        // ---- d1: h @ d1^T -> density (den, half) + sigma (den, f32) ----
        {
            float dacc[MT][2][4];
#pragma unroll
            for (int m = 0; m < MT; m++)
#pragma unroll
                for (int h = 0; h < 2; h++)
#pragma unroll
                    for (int e = 0; e < 4; e++) dacc[m][h][e] = 0.0f;
#pragma unroll
            for (int h = 0; h < 2; h++) {
#pragma unroll
                for (int c = 0; c < 2; c++) {
                    uint4 v = pw_d1[(h * 2 + c) * 32];
#pragma unroll
                    for (int m = 0; m < MT; m++) {
                        mma16816(dacc[m][h], Aa[m][2 * c],     v.x, v.y);
                        mma16816(dacc[m][h], Aa[m][2 * c + 1], v.z, v.w);
                    }
                }
            }
#pragma unroll
            for (int m = 0; m < MT; m++) {
                __half* dm = den + m * 16 * LDD;
                *reinterpret_cast<uint32_t*>(dm + g * LDD + i2) =
                    h2u(dacc[m][0][0], dacc[m][0][1]);
                *reinterpret_cast<uint32_t*>(dm + (g + 8) * LDD + i2) =
                    h2u(dacc[m][0][2], dacc[m][0][3]);
                *reinterpret_cast<uint32_t*>(dm + g * LDD + i2 + 8) =
                    h2u(dacc[m][1][0], dacc[m][1][1]);
                *reinterpret_cast<uint32_t*>(dm + (g + 8) * LDD + i2 + 8) =
                    h2u(dacc[m][1][2], dacc[m][1][3]);
                if (i2 == 0) {  // sigma f32 at half-cols 16..17
                    *reinterpret_cast<float*>(dm + g * LDD + 16)       = dacc[m][0][0];
                    *reinterpret_cast<float*>(dm + (g + 8) * LDD + 16) = dacc[m][0][2];
                }
            }
        }
        __syncwarp();

        // ---- c0 input: k-tile0 = sh (gmem), k-tile1 = shifted density ----
        {
            __half z = __float2half(0.0f);
#pragma unroll
            for (int m = 0; m < MT; m++) {
                const float2* s0 =
                    reinterpret_cast<const float2*>(sh + (row0 + m * 16 + g) * 16);
                const float2* s8 =
                    reinterpret_cast<const float2*>(sh + (row0 + m * 16 + g + 8) * 16);
                float2 v0 = __ldcs(s0 + (i2 >> 1));
                float2 v1 = __ldcs(s8 + (i2 >> 1));
                float2 v2 = __ldcs(s0 + 4 + (i2 >> 1));
                float2 v3 = __ldcs(s8 + 4 + (i2 >> 1));
                Ab[m][0][0] = h2u(v0.x, v0.y);
                Ab[m][0][1] = h2u(v1.x, v1.y);
                Ab[m][0][2] = h2u(v2.x, v2.y);
                Ab[m][0][3] = h2u(v3.x, v3.y);
                const __half* dm = den + m * 16 * LDD;
                // concat col 16+j = d1 col j+1 (shift by one); col 31 -> 0
                __half hiA = (i2 == 6) ? z : dm[g * LDD + i2 + 10];
                __half hiB = (i2 == 6) ? z : dm[(g + 8) * LDD + i2 + 10];
                Ab[m][1][0] = hh2u(dm[g * LDD + i2 + 1],       dm[g * LDD + i2 + 2]);
                Ab[m][1][1] = hh2u(dm[(g + 8) * LDD + i2 + 1], dm[(g + 8) * LDD + i2 + 2]);
                Ab[m][1][2] = hh2u(dm[g * LDD + i2 + 9],       hiA);
                Ab[m][1][3] = hh2u(dm[(g + 8) * LDD + i2 + 9], hiB);
            }
        }

        // ---- c0, c1, c2: register-chained relu layers ----
        layer_chain<2, 4>(Ab, pw_c0, Aa);
        layer_chain<4, 4>(Aa, pw_c1, Ab);
        layer_chain<4, 4>(Ab, pw_c2, Aa);

        // ---- c3: color (cols 0..2 of one 8-wide n-tile) ----
        {
            float cacc[MT][4];
#pragma unroll
            for (int m = 0; m < MT; m++)
#pragma unroll
                for (int e = 0; e < 4; e++) cacc[m][e] = 0.0f;
#pragma unroll
            for (int c = 0; c < 2; c++) {
                uint4 v = pw_c3[c * 32];
#pragma unroll
                for (int m = 0; m < MT; m++) {
                    mma16816(cacc[m], Aa[m][2 * c],     v.x, v.y);
                    mma16816(cacc[m], Aa[m][2 * c + 1], v.z, v.w);
                }
            }
#pragma unroll
            for (int m = 0; m < MT; m++) {
                // lane 4g holds cols {0,1}; lane 4g+1 holds col 2
                float b0c = __shfl_down_sync(0xffffffffu, cacc[m][0], 1);
                float b1c = __shfl_down_sync(0xffffffffu, cacc[m][2], 1);
                if ((lane & 3) == 0) {
                    const __half* dm = den + m * 16 * LDD;
                    float s0 = *reinterpret_cast<const float*>(dm + g * LDD + 16);
                    float s1 = *reinterpret_cast<const float*>(dm + (g + 8) * LDD + 16);
                    out4[row0 + m * 16 + g]     = make_float4(cacc[m][0], cacc[m][1], b0c, s0);
                    out4[row0 + m * 16 + g + 8] = make_float4(cacc[m][2], cacc[m][3], b1c, s1);
                }
            }
        }
        __syncwarp();
    }
}

extern "C" void kernel_launch(void* const* d_in, const int* in_sizes, int n_in,
                              void* d_out, int out_size) {
    const float* hash = (const float*)d_in[0];  // [N, 32]
    const float* sh   = (const float*)d_in[1];  // [N, 16]
    const float* d0   = (const float*)d_in[2];  // [64, 32]
    const float* d1   = (const float*)d_in[3];  // [16, 64]
    const float* c0   = (const float*)d_in[4];  // [64, 31]
    const float* c1   = (const float*)d_in[5];  // [64, 64]
    const float* c2   = (const float*)d_in[6];  // [64, 64]
    const float* c3   = (const float*)d_in[7];  // [3, 64]
    float* out = (float*)d_out;                 // [N, 4]

    const int n       = in_sizes[0] / 32;
    const int n_tiles = n / CTA_M;  // 16384

    int grid = 148 * 5;  // persistent, 5 CTAs/SM, 20 warps/SM
    if (grid > n_tiles) grid = n_tiles;

    nerf_fused_kernel<<<grid, THREADS>>>(hash, sh, d0, d1, c0, c1, c2, c3, out,
                                         n_tiles);
}